// round 15
// baseline (speedup 1.0000x reference)
#include <cuda_runtime.h>

// Problem constants
#define BB     256      // batch
#define SEQ    196
#define DD     768
#define D4     192      // DD/4 float4 per row
#define NPOOL  20       // per pool
#define NKEYS  40       // 20 s-keys + 20 m-keys
#define KK     4        // top-k
#define BLK    3840     // LEN*H*DH = 5*12*64 floats per selected pool entry
#define BLK8   480      // BLK/8 float8-groups per chunk
#define PER_LB 15360    // KK * BLK floats per (layer, batch)
#define L2N    24       // num_layers * 2
#define NGB    (L2N * BB)   // 6144 gather blocks per pool
#define SCHUNKS 4       // seq chunks per batch
#define SROWS   49      // rows per chunk (4*49 = 196)

// Device-global scratch (no allocations; zero-initialized at load)
__device__ float4 g_part[BB * SCHUNKS * D4];  // chunk partial sums (3 MB)
__device__ int    g_cnt[BB];                  // per-batch arrival counters
__device__ int    g_sidx[BB * KK];
__device__ int    g_midx[BB * KK];
__device__ float  g_bsum_s[BB];
__device__ float  g_bsum_m[BB];

// 256-bit global load (non-coherent) / streaming store — sm_100+ PTX.
__device__ __forceinline__ void ldg_nc_v8(const float* p, float* v) {
    asm volatile("ld.global.nc.v8.f32 {%0,%1,%2,%3,%4,%5,%6,%7}, [%8];"
                 : "=f"(v[0]), "=f"(v[1]), "=f"(v[2]), "=f"(v[3]),
                   "=f"(v[4]), "=f"(v[5]), "=f"(v[6]), "=f"(v[7])
                 : "l"(p));
}
__device__ __forceinline__ void stg_cs_v8(float* p, const float* v) {
    asm volatile("st.global.cs.v8.f32 [%0], {%1,%2,%3,%4,%5,%6,%7,%8};"
                 :: "l"(p),
                    "f"(v[0]), "f"(v[1]), "f"(v[2]), "f"(v[3]),
                    "f"(v[4]), "f"(v[5]), "f"(v[6]), "f"(v[7])
                 : "memory");
}

// ---------------------------------------------------------------------------
// Kernel 1: balanced sim. Grid 1024 x 192: block (b,c) sums 49 rows of
// batch b's chunk c (one float4 column per thread, fully coalesced, all
// blocks resident -> 1.2% SM imbalance). Last finisher per batch combines
// the 4 partials in FIXED order (bitwise-deterministic), L2-normalizes,
// does 40 dots with on-the-fly key normalization, top-4, resets counter.
// ---------------------------------------------------------------------------
__global__ void __launch_bounds__(192, 8)
sim_kernel(const float4* __restrict__ x,
           const float4* __restrict__ skey,
           const float4* __restrict__ mkey) {
    int bid = blockIdx.x;
    int b = bid >> 2;               // batch
    int c = bid & 3;                // chunk
    int t = threadIdx.x;            // 0..191

    // Phase A: chunk partial sum (49 coalesced float4 rows, streaming reads)
    const float4* src = x + (size_t)b * (SEQ * D4) + (size_t)(c * SROWS) * D4 + t;
    float4 acc = make_float4(0.f, 0.f, 0.f, 0.f);
    #pragma unroll 7
    for (int r = 0; r < SROWS; ++r) {
        float4 v = __ldcs(&src[(size_t)r * D4]);
        acc.x += v.x; acc.y += v.y; acc.z += v.z; acc.w += v.w;
    }
    g_part[((size_t)b * SCHUNKS + c) * D4 + t] = acc;

    // Publish, then bump the per-batch counter (threadFenceReduction pattern)
    __threadfence();
    __syncthreads();
    __shared__ int s_old;
    if (t == 0) s_old = atomicAdd(&g_cnt[b], 1);
    __syncthreads();
    if (s_old != 3) return;         // not the last finisher

    if (t == 0) {
        g_cnt[b] = 0;               // replay-safe reset (all 4 arrivals done)
        __threadfence();            // acquire side
    }
    __syncthreads();

    // Phase B: combine partials (fixed order) -> mean -> normalize
    __shared__ float4 sh_x4[D4];
    __shared__ float  shw[6];
    __shared__ float  sh_sim[NKEYS];

    const float4* part = g_part + (size_t)b * SCHUNKS * D4;
    float4 p0 = __ldcg(&part[t]);
    float4 p1 = __ldcg(&part[D4 + t]);
    float4 p2 = __ldcg(&part[2 * D4 + t]);
    float4 p3 = __ldcg(&part[3 * D4 + t]);
    float4 m;
    m.x = (p0.x + p1.x + p2.x + p3.x) * (1.0f / SEQ);
    m.y = (p0.y + p1.y + p2.y + p3.y) * (1.0f / SEQ);
    m.z = (p0.z + p1.z + p2.z + p3.z) * (1.0f / SEQ);
    m.w = (p0.w + p1.w + p2.w + p3.w) * (1.0f / SEQ);
    float sq = m.x * m.x + m.y * m.y + m.z * m.z + m.w * m.w;

    int warp = t >> 5, lane = t & 31;
    #pragma unroll
    for (int o = 16; o > 0; o >>= 1) sq += __shfl_down_sync(0xffffffffu, sq, o);
    if (lane == 0) shw[warp] = sq;
    __syncthreads();
    if (t < 32) {
        float v = (t < 6) ? shw[t] : 0.f;
        v += __shfl_down_sync(0xffffffffu, v, 4);
        v += __shfl_down_sync(0xffffffffu, v, 2);
        v += __shfl_down_sync(0xffffffffu, v, 1);
        if (t == 0) shw[0] = v;
    }
    __syncthreads();
    float inv = rsqrtf(fmaxf(shw[0], 1e-12f));
    m.x *= inv; m.y *= inv; m.z *= inv; m.w *= inv;
    sh_x4[t] = m;
    __syncthreads();

    // Phase C: 6 warps handle 40 pools (same association as before)
    for (int p = warp; p < NKEYS; p += 6) {
        const float4* kp = (p < NPOOL) ? (skey + (size_t)p * D4)
                                       : (mkey + (size_t)(p - NPOOL) * D4);
        float dot = 0.f, kk = 0.f;
        #pragma unroll
        for (int i = lane; i < D4; i += 32) {
            float4 xv = sh_x4[i], kv = __ldg(&kp[i]);
            dot += xv.x * kv.x + xv.y * kv.y + xv.z * kv.z + xv.w * kv.w;
            kk  += kv.x * kv.x + kv.y * kv.y + kv.z * kv.z + kv.w * kv.w;
        }
        #pragma unroll
        for (int o = 16; o > 0; o >>= 1) {
            dot += __shfl_down_sync(0xffffffffu, dot, o);
            kk  += __shfl_down_sync(0xffffffffu, kk, o);
        }
        if (lane == 0) sh_sim[p] = dot * rsqrtf(fmaxf(kk, 1e-12f));
    }
    __syncthreads();

    // Phase D: top-4 (descending, first-index ties). t=0: s, t=1: m.
    if (t < 2) {
        const float* sims = sh_sim + t * NPOOL;
        int* idx = t ? g_midx : g_sidx;
        float v[NPOOL];
        #pragma unroll
        for (int j = 0; j < NPOOL; ++j) v[j] = sims[j];
        float sum = 0.f;
        #pragma unroll
        for (int k = 0; k < KK; ++k) {
            float best = -1e30f; int bi = 0;
            #pragma unroll
            for (int j = 0; j < NPOOL; ++j) if (v[j] > best) { best = v[j]; bi = j; }
            idx[b * KK + k] = bi;
            sum += best;
            v[bi] = -1e30f;
        }
        if (t) g_bsum_m[b] = sum; else g_bsum_s[b] = sum;
    }
}

// ---------------------------------------------------------------------------
// Kernel 2: fused gather — EXACT R14 configuration (measured 110.7us,
// 80.9% DRAM). Grid 12288 x 480; one v8-group per thread per chunk,
// 4 loads then 4 stores. Block 0 folds in the scalar reduction.
// ---------------------------------------------------------------------------
__global__ void __launch_bounds__(480)
gather_kernel(const float* __restrict__ s_prompt,
              const float* __restrict__ m_prompt,
              float* __restrict__ out,
              float* __restrict__ out_scalars) {
    int g = blockIdx.x;               // 0..12287
    int which = g >= NGB;
    int lb = which ? g - NGB : g;
    int l = lb >> 8;                  // / 256
    int b = lb & 255;
    int t = threadIdx.x;              // 0..479

    if (g == 0) {
        __shared__ float shs[8], shm[8];
        float ssum = (t < BB) ? g_bsum_s[t] : 0.f;
        float msum = (t < BB) ? g_bsum_m[t] : 0.f;
        #pragma unroll
        for (int o = 16; o > 0; o >>= 1) {
            ssum += __shfl_down_sync(0xffffffffu, ssum, o);
            msum += __shfl_down_sync(0xffffffffu, msum, o);
        }
        if (t < BB && (t & 31) == 0) { shs[t >> 5] = ssum; shm[t >> 5] = msum; }
        __syncthreads();
        if (t == 0) {
            float sv = 0.f, mv = 0.f;
            #pragma unroll
            for (int w = 0; w < 8; ++w) { sv += shs[w]; mv += shm[w]; }
            out_scalars[0] = sv * (1.0f / BB);
            out_scalars[1] = mv * (1.0f / BB);
        }
    }

    const int* idx = which ? g_midx : g_sidx;
    const float* prompt = which ? m_prompt : s_prompt;
    const float* lbase = prompt + (size_t)l * NPOOL * BLK;

    int i0 = idx[b * KK + 0], i1 = idx[b * KK + 1],
        i2 = idx[b * KK + 2], i3 = idx[b * KK + 3];

    float* dst = out + (size_t)g * PER_LB + (size_t)t * 8;

    float a[8], c[8], d[8], e[8];
    ldg_nc_v8(lbase + (size_t)i0 * BLK + (size_t)t * 8, a);
    ldg_nc_v8(lbase + (size_t)i1 * BLK + (size_t)t * 8, c);
    ldg_nc_v8(lbase + (size_t)i2 * BLK + (size_t)t * 8, d);
    ldg_nc_v8(lbase + (size_t)i3 * BLK + (size_t)t * 8, e);
    stg_cs_v8(dst,            a);
    stg_cs_v8(dst + BLK,      c);
    stg_cs_v8(dst + 2 * BLK,  d);
    stg_cs_v8(dst + 3 * BLK,  e);
}

// ---------------------------------------------------------------------------
extern "C" void kernel_launch(void* const* d_in, const int* in_sizes, int n_in,
                              void* d_out, int out_size) {
    const float* x_embed = (const float*)d_in[0];  // [256,196,768]
    const float* s_prompt = (const float*)d_in[1]; // [24,20,5,12,64]
    const float* m_prompt = (const float*)d_in[2]; // [24,20,5,12,64]
    const float* s_key = (const float*)d_in[3];    // [20,768]
    const float* m_key = (const float*)d_in[4];    // [20,768]
    float* out = (float*)d_out;

    const size_t S_ELEMS = (size_t)L2N * BB * PER_LB;  // 94,371,840
    float* out_scalars = out + 2 * S_ELEMS;

    sim_kernel<<<BB * SCHUNKS, 192>>>((const float4*)x_embed,
                                      (const float4*)s_key,
                                      (const float4*)m_key);
    gather_kernel<<<2 * NGB, 480>>>(s_prompt, m_prompt, out, out_scalars);
}

// round 16
// speedup vs baseline: 1.0121x; 1.0121x over previous
#include <cuda_runtime.h>

// Problem constants
#define BB     256      // batch
#define SEQ    196
#define DD     768
#define D4     192      // DD/4 float4 per row
#define D8     96       // DD/8 float8-groups per row
#define NPOOL  20       // per pool
#define NKEYS  40       // 20 s-keys + 20 m-keys
#define KK     4        // top-k
#define BLK    3840     // LEN*H*DH = 5*12*64 floats per selected pool entry
#define PER_LB 15360    // KK * BLK floats per (layer, batch)
#define L2N    24       // num_layers * 2
#define NGB    (L2N * BB)   // 6144 gather blocks per pool

// Device-global scratch (no allocations allowed)
__device__ int   g_sidx[BB * KK];
__device__ int   g_midx[BB * KK];
__device__ float g_bsum_s[BB];         // per-batch sum of top-4 s sims
__device__ float g_bsum_m[BB];         // per-batch sum of top-4 m sims

// 256-bit global loads/stores — sm_100+ PTX (ISA 8.8).
__device__ __forceinline__ void ldg_nc_v8(const float* p, float* v) {
    asm volatile("ld.global.nc.v8.f32 {%0,%1,%2,%3,%4,%5,%6,%7}, [%8];"
                 : "=f"(v[0]), "=f"(v[1]), "=f"(v[2]), "=f"(v[3]),
                   "=f"(v[4]), "=f"(v[5]), "=f"(v[6]), "=f"(v[7])
                 : "l"(p));
}
__device__ __forceinline__ void ldg_cs_v8(const float* p, float* v) {
    asm volatile("ld.global.cs.v8.f32 {%0,%1,%2,%3,%4,%5,%6,%7}, [%8];"
                 : "=f"(v[0]), "=f"(v[1]), "=f"(v[2]), "=f"(v[3]),
                   "=f"(v[4]), "=f"(v[5]), "=f"(v[6]), "=f"(v[7])
                 : "l"(p));
}
__device__ __forceinline__ void stg_cs_v8(float* p, const float* v) {
    asm volatile("st.global.cs.v8.f32 [%0], {%1,%2,%3,%4,%5,%6,%7,%8};"
                 :: "l"(p),
                    "f"(v[0]), "f"(v[1]), "f"(v[2]), "f"(v[3]),
                    "f"(v[4]), "f"(v[5]), "f"(v[6]), "f"(v[7])
                 : "memory");
}

// ---------------------------------------------------------------------------
// Kernel 1: fused per-batch mean + L2-normalize + 40 sims (on-the-fly key
// normalization) + top-4. R14 structure, but phase A uses 256-bit streaming
// loads: 768 threads = 96 v8-col-groups x 8 row-octants (25,25,25,25,
// 24,24,24,24 rows; each warp inside one octant). Fixed-order combine.
// 256 blocks x 768 threads.
// ---------------------------------------------------------------------------
__global__ void batch_sim_topk_kernel(const float* __restrict__ x,
                                      const float4* __restrict__ skey,
                                      const float4* __restrict__ mkey) {
    int b = blockIdx.x;
    int t = threadIdx.x;    // 0..767
    int o = t / D8;         // row octant 0..7 (warp-uniform: 96 = 3 warps)
    int c8 = t % D8;        // v8 column group 0..95

    __shared__ float  sh[8 * 768];   // octant partials, sh[i*768 + o*96 + c8] (24 KB)
    __shared__ float4 sh_x4[D4];     // normalized mean (3 KB)
    __shared__ float  shw[3];
    __shared__ float  sh_sim[NKEYS];

    // Phase A: per-octant column sums with 32B streaming loads.
    int rows  = (o < 4) ? 25 : 24;
    int start = o * 24 + ((o < 4) ? o : 4);
    const float* src = x + (size_t)b * (SEQ * DD) + (size_t)start * DD + c8 * 8;
    float a[8];
    #pragma unroll
    for (int i = 0; i < 8; ++i) a[i] = 0.f;
    for (int r = 0; r < rows; ++r) {
        float v[8];
        ldg_cs_v8(src + (size_t)r * DD, v);
        #pragma unroll
        for (int i = 0; i < 8; ++i) a[i] += v[i];
    }
    #pragma unroll
    for (int i = 0; i < 8; ++i) sh[i * 768 + t] = a[i];
    __syncthreads();

    // Phase B: combine 8 octants (fixed order) -> mean; squared-norm partial.
    float sq = 0.f;
    float m[8];
    if (t < D8) {
        #pragma unroll
        for (int i = 0; i < 8; ++i) {
            float s = 0.f;
            #pragma unroll
            for (int oo = 0; oo < 8; ++oo) s += sh[i * 768 + oo * D8 + t];
            m[i] = s * (1.0f / SEQ);
            sq += m[i] * m[i];
        }
    }
    #pragma unroll
    for (int off = 16; off > 0; off >>= 1) sq += __shfl_down_sync(0xffffffffu, sq, off);
    if (t < D8 && (t & 31) == 0) shw[t >> 5] = sq;
    __syncthreads();
    float inv;
    {
        __shared__ float s_inv;
        if (t == 0) s_inv = rsqrtf(fmaxf(shw[0] + shw[1] + shw[2], 1e-12f));
        __syncthreads();
        inv = s_inv;
    }
    if (t < D8) {
        float4 lo, hi;
        lo.x = m[0] * inv; lo.y = m[1] * inv; lo.z = m[2] * inv; lo.w = m[3] * inv;
        hi.x = m[4] * inv; hi.y = m[5] * inv; hi.z = m[6] * inv; hi.w = m[7] * inv;
        sh_x4[2 * t]     = lo;
        sh_x4[2 * t + 1] = hi;
    }
    __syncthreads();

    // Phase C: 24 warps handle 40 pools (raw-key dot + key norm in one pass).
    int warp = t >> 5, lane = t & 31;
    for (int p = warp; p < NKEYS; p += 24) {
        const float4* kp = (p < NPOOL) ? (skey + (size_t)p * D4)
                                       : (mkey + (size_t)(p - NPOOL) * D4);
        float dot = 0.f, kk = 0.f;
        #pragma unroll
        for (int i = lane; i < D4; i += 32) {
            float4 xv = sh_x4[i], kv = __ldg(&kp[i]);
            dot += xv.x * kv.x + xv.y * kv.y + xv.z * kv.z + xv.w * kv.w;
            kk  += kv.x * kv.x + kv.y * kv.y + kv.z * kv.z + kv.w * kv.w;
        }
        #pragma unroll
        for (int off = 16; off > 0; off >>= 1) {
            dot += __shfl_down_sync(0xffffffffu, dot, off);
            kk  += __shfl_down_sync(0xffffffffu, kk, off);
        }
        if (lane == 0) sh_sim[p] = dot * rsqrtf(fmaxf(kk, 1e-12f));
    }
    __syncthreads();

    // Phase D: top-4 (descending, first-index ties — strict > scan from j=0).
    if (t < 2) {
        const float* sims = sh_sim + t * NPOOL;
        int* idx = t ? g_midx : g_sidx;
        float v[NPOOL];
        #pragma unroll
        for (int j = 0; j < NPOOL; ++j) v[j] = sims[j];
        float sum = 0.f;
        #pragma unroll
        for (int k = 0; k < KK; ++k) {
            float best = -1e30f; int bi = 0;
            #pragma unroll
            for (int j = 0; j < NPOOL; ++j) if (v[j] > best) { best = v[j]; bi = j; }
            idx[b * KK + k] = bi;
            sum += best;
            v[bi] = -1e30f;
        }
        if (t) g_bsum_m[b] = sum; else g_bsum_s[b] = sum;
    }
}

// ---------------------------------------------------------------------------
// Kernel 2: fused gather — EXACT R14 configuration (measured 110.7us,
// 80.9% DRAM — at the HBM write-stream ceiling). Grid 12288 x 480; one
// v8-group per thread per chunk, 4 loads then 4 stores. Block 0 folds in
// the scalar reduction.
// ---------------------------------------------------------------------------
__global__ void __launch_bounds__(480)
gather_kernel(const float* __restrict__ s_prompt,
              const float* __restrict__ m_prompt,
              float* __restrict__ out,
              float* __restrict__ out_scalars) {
    int g = blockIdx.x;               // 0..12287
    int which = g >= NGB;
    int lb = which ? g - NGB : g;
    int l = lb >> 8;                  // / 256
    int b = lb & 255;
    int t = threadIdx.x;              // 0..479

    if (g == 0) {
        __shared__ float shs[8], shm[8];
        float ssum = (t < BB) ? g_bsum_s[t] : 0.f;
        float msum = (t < BB) ? g_bsum_m[t] : 0.f;
        #pragma unroll
        for (int o = 16; o > 0; o >>= 1) {
            ssum += __shfl_down_sync(0xffffffffu, ssum, o);
            msum += __shfl_down_sync(0xffffffffu, msum, o);
        }
        if (t < BB && (t & 31) == 0) { shs[t >> 5] = ssum; shm[t >> 5] = msum; }
        __syncthreads();
        if (t == 0) {
            float sv = 0.f, mv = 0.f;
            #pragma unroll
            for (int w = 0; w < 8; ++w) { sv += shs[w]; mv += shm[w]; }
            out_scalars[0] = sv * (1.0f / BB);
            out_scalars[1] = mv * (1.0f / BB);
        }
    }

    const int* idx = which ? g_midx : g_sidx;
    const float* prompt = which ? m_prompt : s_prompt;
    const float* lbase = prompt + (size_t)l * NPOOL * BLK;

    int i0 = idx[b * KK + 0], i1 = idx[b * KK + 1],
        i2 = idx[b * KK + 2], i3 = idx[b * KK + 3];

    float* dst = out + (size_t)g * PER_LB + (size_t)t * 8;

    float a[8], c[8], d[8], e[8];
    ldg_nc_v8(lbase + (size_t)i0 * BLK + (size_t)t * 8, a);
    ldg_nc_v8(lbase + (size_t)i1 * BLK + (size_t)t * 8, c);
    ldg_nc_v8(lbase + (size_t)i2 * BLK + (size_t)t * 8, d);
    ldg_nc_v8(lbase + (size_t)i3 * BLK + (size_t)t * 8, e);
    stg_cs_v8(dst,            a);
    stg_cs_v8(dst + BLK,      c);
    stg_cs_v8(dst + 2 * BLK,  d);
    stg_cs_v8(dst + 3 * BLK,  e);
}

// ---------------------------------------------------------------------------
extern "C" void kernel_launch(void* const* d_in, const int* in_sizes, int n_in,
                              void* d_out, int out_size) {
    const float* x_embed = (const float*)d_in[0];  // [256,196,768]
    const float* s_prompt = (const float*)d_in[1]; // [24,20,5,12,64]
    const float* m_prompt = (const float*)d_in[2]; // [24,20,5,12,64]
    const float* s_key = (const float*)d_in[3];    // [20,768]
    const float* m_key = (const float*)d_in[4];    // [20,768]
    float* out = (float*)d_out;

    const size_t S_ELEMS = (size_t)L2N * BB * PER_LB;  // 94,371,840
    float* out_scalars = out + 2 * S_ELEMS;

    batch_sim_topk_kernel<<<BB, 768>>>(x_embed,
                                       (const float4*)s_key,
                                       (const float4*)m_key);
    gather_kernel<<<2 * NGB, 480>>>(s_prompt, m_prompt, out, out_scalars);
}

// round 17
// speedup vs baseline: 1.0682x; 1.0554x over previous
#include <cuda_runtime.h>

// Problem constants
#define BB     256      // batch
#define SEQ    196
#define DD     768
#define D4     192      // DD/4 float4 per row
#define NPOOL  20       // per pool
#define NKEYS  40       // 20 s-keys + 20 m-keys
#define KK     4        // top-k
#define BLK    3840     // LEN*H*DH = 5*12*64 floats per selected pool entry
#define PER_LB 15360    // KK * BLK floats per (layer, batch)
#define L2N    24       // num_layers * 2
#define NGB    (L2N * BB)   // 6144 gather blocks per pool

// Device-global scratch (no allocations allowed)
__device__ int   g_sidx[BB * KK];
__device__ int   g_midx[BB * KK];
__device__ float g_bsum_s[BB];         // per-batch sum of top-4 s sims
__device__ float g_bsum_m[BB];         // per-batch sum of top-4 m sims

// 256-bit global load (non-coherent) / streaming store — sm_100+ PTX.
__device__ __forceinline__ void ldg_nc_v8(const float* p, float* v) {
    asm volatile("ld.global.nc.v8.f32 {%0,%1,%2,%3,%4,%5,%6,%7}, [%8];"
                 : "=f"(v[0]), "=f"(v[1]), "=f"(v[2]), "=f"(v[3]),
                   "=f"(v[4]), "=f"(v[5]), "=f"(v[6]), "=f"(v[7])
                 : "l"(p));
}
__device__ __forceinline__ void stg_cs_v8(float* p, const float* v) {
    asm volatile("st.global.cs.v8.f32 [%0], {%1,%2,%3,%4,%5,%6,%7,%8};"
                 :: "l"(p),
                    "f"(v[0]), "f"(v[1]), "f"(v[2]), "f"(v[3]),
                    "f"(v[4]), "f"(v[5]), "f"(v[6]), "f"(v[7])
                 : "memory");
}

// ---------------------------------------------------------------------------
// Kernel 1: fused per-batch mean (float4, 4 row-groups of 49) + L2-normalize
// + 40 similarity dots with on-the-fly key normalization + top-4 selection.
// Measured 29.8us (imbalance-limited read ceiling: 256 blocks on 148 SMs).
// 256 blocks x 768 threads. __ldcs streaming reads of x.
// ---------------------------------------------------------------------------
__global__ void batch_sim_topk_kernel(const float4* __restrict__ x,
                                      const float4* __restrict__ skey,
                                      const float4* __restrict__ mkey) {
    int b = blockIdx.x;
    int t = threadIdx.x;   // 0..767
    int q = t / D4;        // row quarter 0..3 (49 rows each)
    int c4 = t % D4;       // float4 column 0..191

    __shared__ float4 sh4[768];     // partial sums (12 KB)
    __shared__ float4 sh_x4[D4];    // normalized mean (3 KB)
    __shared__ float  shw[8];
    __shared__ float  sh_sim[NKEYS];

    const float4* src = x + (size_t)b * (SEQ * D4) + (size_t)(q * 49) * D4 + c4;
    float4 acc = make_float4(0.f, 0.f, 0.f, 0.f);
    #pragma unroll 7
    for (int r = 0; r < 49; ++r) {
        float4 v = __ldcs(&src[(size_t)r * D4]);   // streaming (evict-first)
        acc.x += v.x; acc.y += v.y; acc.z += v.z; acc.w += v.w;
    }
    sh4[t] = acc;
    __syncthreads();

    float sq = 0.f;
    if (t < D4) {
        float4 a = sh4[t], b1 = sh4[t + D4], c = sh4[t + 2 * D4], d = sh4[t + 3 * D4];
        float4 m;
        m.x = (a.x + b1.x + c.x + d.x) * (1.0f / SEQ);
        m.y = (a.y + b1.y + c.y + d.y) * (1.0f / SEQ);
        m.z = (a.z + b1.z + c.z + d.z) * (1.0f / SEQ);
        m.w = (a.w + b1.w + c.w + d.w) * (1.0f / SEQ);
        sh_x4[t] = m;
        sq = m.x * m.x + m.y * m.y + m.z * m.z + m.w * m.w;
    }
    #pragma unroll
    for (int o = 16; o > 0; o >>= 1) sq += __shfl_down_sync(0xffffffffu, sq, o);
    if (t < D4 && (t & 31) == 0) shw[t >> 5] = sq;
    __syncthreads();
    if (t < 32) {
        float v = (t < 6) ? shw[t] : 0.f;
        #pragma unroll
        for (int o = 4; o > 0; o >>= 1) v += __shfl_down_sync(0xffffffffu, v, o);
        if (t == 0) shw[0] = v;
    }
    __syncthreads();
    float inv = rsqrtf(fmaxf(shw[0], 1e-12f));
    if (t < D4) {
        float4 m = sh_x4[t];
        m.x *= inv; m.y *= inv; m.z *= inv; m.w *= inv;
        sh_x4[t] = m;
    }
    __syncthreads();

    int warp = t >> 5, lane = t & 31;
    for (int p = warp; p < NKEYS; p += 24) {
        const float4* kp = (p < NPOOL) ? (skey + (size_t)p * D4)
                                       : (mkey + (size_t)(p - NPOOL) * D4);
        float dot = 0.f, kk = 0.f;
        #pragma unroll
        for (int i = lane; i < D4; i += 32) {
            float4 xv = sh_x4[i], kv = __ldg(&kp[i]);
            dot += xv.x * kv.x + xv.y * kv.y + xv.z * kv.z + xv.w * kv.w;
            kk  += kv.x * kv.x + kv.y * kv.y + kv.z * kv.z + kv.w * kv.w;
        }
        #pragma unroll
        for (int o = 16; o > 0; o >>= 1) {
            dot += __shfl_down_sync(0xffffffffu, dot, o);
            kk  += __shfl_down_sync(0xffffffffu, kk, o);
        }
        if (lane == 0) sh_sim[p] = dot * rsqrtf(fmaxf(kk, 1e-12f));
    }
    __syncthreads();

    // Top-4 (descending, first-index ties — strict > scan from j=0).
    if (t < 2) {
        const float* sims = sh_sim + t * NPOOL;
        int* idx = t ? g_midx : g_sidx;
        float v[NPOOL];
        #pragma unroll
        for (int j = 0; j < NPOOL; ++j) v[j] = sims[j];
        float sum = 0.f;
        #pragma unroll
        for (int k = 0; k < KK; ++k) {
            float best = -1e30f; int bi = 0;
            #pragma unroll
            for (int j = 0; j < NPOOL; ++j) if (v[j] > best) { best = v[j]; bi = j; }
            idx[b * KK + k] = bi;
            sum += best;
            v[bi] = -1e30f;
        }
        if (t) g_bsum_m[b] = sum; else g_bsum_s[b] = sum;
    }
}

// ---------------------------------------------------------------------------
// Kernel 2: fused gather — measured 109.4-110.7us at 80.9-81.8% DRAM (the
// HBM write-stream ceiling, triple-confirmed). Grid 12288 x 480; one
// v8-group per thread per chunk, 4 independent loads (MLP=4) then 4 stores.
// Block 0 folds in the scalar reduction.
// ---------------------------------------------------------------------------
__global__ void __launch_bounds__(480)
gather_kernel(const float* __restrict__ s_prompt,
              const float* __restrict__ m_prompt,
              float* __restrict__ out,
              float* __restrict__ out_scalars) {
    int g = blockIdx.x;               // 0..12287
    int which = g >= NGB;
    int lb = which ? g - NGB : g;
    int l = lb >> 8;                  // / 256
    int b = lb & 255;
    int t = threadIdx.x;              // 0..479

    if (g == 0) {
        __shared__ float shs[8], shm[8];
        float ssum = (t < BB) ? g_bsum_s[t] : 0.f;
        float msum = (t < BB) ? g_bsum_m[t] : 0.f;
        #pragma unroll
        for (int o = 16; o > 0; o >>= 1) {
            ssum += __shfl_down_sync(0xffffffffu, ssum, o);
            msum += __shfl_down_sync(0xffffffffu, msum, o);
        }
        if (t < BB && (t & 31) == 0) { shs[t >> 5] = ssum; shm[t >> 5] = msum; }
        __syncthreads();
        if (t == 0) {
            float sv = 0.f, mv = 0.f;
            #pragma unroll
            for (int w = 0; w < 8; ++w) { sv += shs[w]; mv += shm[w]; }
            out_scalars[0] = sv * (1.0f / BB);
            out_scalars[1] = mv * (1.0f / BB);
        }
    }

    const int* idx = which ? g_midx : g_sidx;
    const float* prompt = which ? m_prompt : s_prompt;
    const float* lbase = prompt + (size_t)l * NPOOL * BLK;

    int i0 = idx[b * KK + 0], i1 = idx[b * KK + 1],
        i2 = idx[b * KK + 2], i3 = idx[b * KK + 3];

    float* dst = out + (size_t)g * PER_LB + (size_t)t * 8;

    float a[8], c[8], d[8], e[8];
    ldg_nc_v8(lbase + (size_t)i0 * BLK + (size_t)t * 8, a);
    ldg_nc_v8(lbase + (size_t)i1 * BLK + (size_t)t * 8, c);
    ldg_nc_v8(lbase + (size_t)i2 * BLK + (size_t)t * 8, d);
    ldg_nc_v8(lbase + (size_t)i3 * BLK + (size_t)t * 8, e);
    stg_cs_v8(dst,            a);
    stg_cs_v8(dst + BLK,      c);
    stg_cs_v8(dst + 2 * BLK,  d);
    stg_cs_v8(dst + 3 * BLK,  e);
}

// ---------------------------------------------------------------------------
extern "C" void kernel_launch(void* const* d_in, const int* in_sizes, int n_in,
                              void* d_out, int out_size) {
    const float* x_embed = (const float*)d_in[0];  // [256,196,768]
    const float* s_prompt = (const float*)d_in[1]; // [24,20,5,12,64]
    const float* m_prompt = (const float*)d_in[2]; // [24,20,5,12,64]
    const float* s_key = (const float*)d_in[3];    // [20,768]
    const float* m_key = (const float*)d_in[4];    // [20,768]
    float* out = (float*)d_out;

    const size_t S_ELEMS = (size_t)L2N * BB * PER_LB;  // 94,371,840
    float* out_scalars = out + 2 * S_ELEMS;

    batch_sim_topk_kernel<<<BB, 768>>>((const float4*)x_embed,
                                       (const float4*)s_key,
                                       (const float4*)m_key);
    gather_kernel<<<2 * NGB, 480>>>(s_prompt, m_prompt, out, out_scalars);
}